// round 1
// baseline (speedup 1.0000x reference)
#include <cuda_runtime.h>
#include <cuda_bf16.h>
#include <math.h>

// ---------------------------------------------------------------------------
// Problem constants: x(2,4,1024,1024), HEADS=8, D=128, ROT_DIM=64
// ---------------------------------------------------------------------------
#define BATCH   2
#define CH      4
#define BC      (BATCH*CH)        // 8
#define NB      1024              // BINS
#define NH      8                 // heads
#define HD      128               // head dim
#define BCN     (BC*NH)           // 64
#define ROT     64                // rotary dims

// Scratch (static __device__ — no allocations allowed)
__device__ float g_y [BC  * NB * NB];   // proj gemm out (pre-conv)      32MB
__device__ float g_p [BC  * NB * NB];   // conv+bias out ("ph", also V^T) 32MB
__device__ float g_q [BCN * NB * HD];   // roped Q (= K)                  32MB
__device__ float g_s [BCN * NB * NB];   // attention scores              256MB
__device__ float g_av[BCN * NB * HD];   // softmax @ V                    32MB
__device__ float g_am[BC  * NB * NB];   // merged heads (h-major)         32MB

// ---------------------------------------------------------------------------
// Generic batched NT SGEMM: C[m,n] = sum_k A[m*lda+k] * B[n*ldb+k]
// BM=BN=128, BK=8, 256 threads, 8x8 per-thread microtile.
// B batch pointer = B + (batch % modB) * sB  (weights shared across b).
// ---------------------------------------------------------------------------
__global__ __launch_bounds__(256)
void sgemm_nt(const float* __restrict__ A, const float* __restrict__ B,
              float* __restrict__ C,
              int M, int N, int K, int lda, int ldb, int ldc,
              long sA, long sB, long sC, int modB)
{
    const int batch = blockIdx.z;
    A += (long)batch * sA;
    B += (long)(batch % modB) * sB;
    C += (long)batch * sC;

    __shared__ float As[8][128];
    __shared__ float Bs[8][128];

    const int bm = blockIdx.y * 128;
    const int bn = blockIdx.x * 128;
    const int tid = threadIdx.x;

    // global load mapping: 128 rows x 8 k -> 2 float4 per row, 256 threads
    const int lrow = tid >> 1;
    const int lcol = (tid & 1) * 4;

    const float* Aptr = A + (long)(bm + lrow) * lda + lcol;
    const float* Bptr = B + (long)(bn + lrow) * ldb + lcol;

    const int trow = (tid >> 4) * 8;   // 0..120
    const int tcol = (tid & 15) * 8;   // 0..120

    float acc[8][8];
    #pragma unroll
    for (int i = 0; i < 8; i++)
        #pragma unroll
        for (int j = 0; j < 8; j++) acc[i][j] = 0.f;

    for (int k0 = 0; k0 < K; k0 += 8) {
        float4 a4 = *(const float4*)(Aptr + k0);
        float4 b4 = *(const float4*)(Bptr + k0);
        __syncthreads();
        As[lcol+0][lrow] = a4.x; As[lcol+1][lrow] = a4.y;
        As[lcol+2][lrow] = a4.z; As[lcol+3][lrow] = a4.w;
        Bs[lcol+0][lrow] = b4.x; Bs[lcol+1][lrow] = b4.y;
        Bs[lcol+2][lrow] = b4.z; Bs[lcol+3][lrow] = b4.w;
        __syncthreads();
        #pragma unroll
        for (int k = 0; k < 8; k++) {
            float ar[8], br[8];
            #pragma unroll
            for (int i = 0; i < 8; i++) ar[i] = As[k][trow + i];
            #pragma unroll
            for (int j = 0; j < 8; j++) br[j] = Bs[k][tcol + j];
            #pragma unroll
            for (int i = 0; i < 8; i++)
                #pragma unroll
                for (int j = 0; j < 8; j++)
                    acc[i][j] = fmaf(ar[i], br[j], acc[i][j]);
        }
    }

    #pragma unroll
    for (int i = 0; i < 8; i++) {
        float* crow = C + (long)(bm + trow + i) * ldc + bn + tcol;
        #pragma unroll
        for (int j = 0; j < 8; j += 4) {
            float4 v = make_float4(acc[i][j], acc[i][j+1], acc[i][j+2], acc[i][j+3]);
            *(float4*)(crow + j) = v;
        }
    }
}

// ---------------------------------------------------------------------------
// Depthwise conv (kernel 3, pad 1 along last axis) + bias
// p[bc][h][o] = y[o-1]*w0 + y[o]*w1 + y[o+1]*w2 + bias[c]
// ---------------------------------------------------------------------------
__global__ __launch_bounds__(256)
void conv_bias(const float* __restrict__ y, const float* __restrict__ wc,
               const float* __restrict__ bias, float* __restrict__ p)
{
    long idx = (long)blockIdx.x * blockDim.x + threadIdx.x;   // 8M elems
    if (idx >= (long)BC * NB * NB) return;
    int o = (int)(idx & (NB - 1));
    int c = (int)((idx >> 20) & 3);   // idx / (1024*1024) % 4
    float w0 = wc[c*3+0], w1 = wc[c*3+1], w2 = wc[c*3+2];
    float mid = y[idx];
    float lft = (o > 0)      ? y[idx - 1] : 0.f;
    float rgt = (o < NB - 1) ? y[idx + 1] : 0.f;
    p[idx] = fmaf(lft, w0, fmaf(mid, w1, fmaf(rgt, w2, bias[c])));
}

// ---------------------------------------------------------------------------
// RoPE + transpose: Q[bcn][s][d] from p[bc][n*128+d][s].
// One thread per (bcn, j, s), j in [0,64): j<32 handles the rotary pair
// (2j,2j+1); j>=32 copies pass-through pair. s fastest -> coalesced reads.
// ---------------------------------------------------------------------------
__global__ __launch_bounds__(256)
void rope_build(const float* __restrict__ p, float* __restrict__ Q)
{
    long idx = (long)blockIdx.x * blockDim.x + threadIdx.x;   // 64*64*1024 = 4M
    if (idx >= (long)BCN * 64 * NB) return;
    int s   = (int)(idx & (NB - 1));
    int j   = (int)((idx >> 10) & 63);
    int bcn = (int)(idx >> 16);
    int bc = bcn >> 3, n = bcn & 7;

    const float* src = p + ((long)bc * NB + n * HD) * NB + s;  // [d] stride = NB
    float*       dst = Q + (long)bcn * (NB * HD) + (long)s * HD;

    if (j < 32) {
        float t0 = src[(2*j + 0) * NB];
        float t1 = src[(2*j + 1) * NB];
        float invf = powf(10000.f, -(float)(2*j) / (float)ROT);
        float ang = (float)s * invf;
        float cs = cosf(ang), sn = sinf(ang);
        dst[2*j + 0] = t0 * cs - t1 * sn;
        dst[2*j + 1] = t1 * cs + t0 * sn;
    } else {
        int d = ROT + (j - 32) * 2;
        dst[d + 0] = src[(d + 0) * NB];
        dst[d + 1] = src[(d + 1) * NB];
    }
}

// ---------------------------------------------------------------------------
// Row softmax with scale (one block per row of 1024)
// ---------------------------------------------------------------------------
__global__ __launch_bounds__(256)
void softmax_rows(float* __restrict__ S, float scale)
{
    float* row = S + (long)blockIdx.x * NB;
    const int t = threadIdx.x;
    __shared__ float red[32];

    float v[4];
    float m = -1e30f;
    #pragma unroll
    for (int i = 0; i < 4; i++) {
        v[i] = row[t + i * 256] * scale;
        m = fmaxf(m, v[i]);
    }
    // block max
    #pragma unroll
    for (int o = 16; o > 0; o >>= 1) m = fmaxf(m, __shfl_xor_sync(~0u, m, o));
    if ((t & 31) == 0) red[t >> 5] = m;
    __syncthreads();
    if (t < 32) {
        float x = red[t & 7];
        #pragma unroll
        for (int o = 4; o > 0; o >>= 1) x = fmaxf(x, __shfl_xor_sync(~0u, x, o));
        red[t] = x;
    }
    __syncthreads();
    m = red[0];

    float sum = 0.f;
    #pragma unroll
    for (int i = 0; i < 4; i++) { v[i] = __expf(v[i] - m); sum += v[i]; }
    #pragma unroll
    for (int o = 16; o > 0; o >>= 1) sum += __shfl_xor_sync(~0u, sum, o);
    __syncthreads();
    if ((t & 31) == 0) red[t >> 5] = sum;
    __syncthreads();
    if (t < 32) {
        float x = red[t & 7];
        #pragma unroll
        for (int o = 4; o > 0; o >>= 1) x += __shfl_xor_sync(~0u, x, o);
        red[t] = x;
    }
    __syncthreads();
    float inv = 1.f / red[0];
    #pragma unroll
    for (int i = 0; i < 4; i++) row[t + i * 256] = v[i] * inv;
}

// ---------------------------------------------------------------------------
// Merge heads: a_m[bc][n*128+d][s] = av[bcn][s][d]   (batched 1024x128 -> T)
// grid (d-tiles=4, s-tiles=32, bcn=64), block (32,8)
// ---------------------------------------------------------------------------
__global__ __launch_bounds__(256)
void merge_heads(const float* __restrict__ av, float* __restrict__ am)
{
    __shared__ float tile[32][33];
    int bcn = blockIdx.z;
    const float* src = av + (long)bcn * (NB * HD);
    float*       dst = am + (long)bcn * (NB * HD);  // bc*1048576 + n*131072 == bcn*131072
    int d0 = blockIdx.x * 32, s0 = blockIdx.y * 32;
    int tx = threadIdx.x, ty = threadIdx.y;
    #pragma unroll
    for (int i = 0; i < 32; i += 8)
        tile[ty + i][tx] = src[(long)(s0 + ty + i) * HD + d0 + tx];
    __syncthreads();
    #pragma unroll
    for (int i = 0; i < 32; i += 8)
        dst[(long)(d0 + ty + i) * NB + s0 + tx] = tile[tx][ty + i];
}

// ---------------------------------------------------------------------------
// Launch
// ---------------------------------------------------------------------------
extern "C" void kernel_launch(void* const* d_in, const int* in_sizes, int n_in,
                              void* d_out, int out_size)
{
    const float* x      = (const float*)d_in[0];  // (2,4,1024,1024)
    const float* w_lin  = (const float*)d_in[1];  // (4,1024,1024)
    const float* w_conv = (const float*)d_in[2];  // (4,1,1,3)
    const float* b_conv = (const float*)d_in[3];  // (4,)
    const float* w_out  = (const float*)d_in[4];  // (4,1024,1024)
    float* out = (float*)d_out;

    float *y, *p, *q, *s, *av, *am;
    cudaGetSymbolAddress((void**)&y,  g_y);
    cudaGetSymbolAddress((void**)&p,  g_p);
    cudaGetSymbolAddress((void**)&q,  g_q);
    cudaGetSymbolAddress((void**)&s,  g_s);
    cudaGetSymbolAddress((void**)&av, g_av);
    cudaGetSymbolAddress((void**)&am, g_am);

    const long MM = (long)NB * NB;          // 1048576
    const long QS = (long)NB * HD;          // 131072

    // 1) proj GEMM: y[bc] = x[bc] @ w_lin[c]^T
    sgemm_nt<<<dim3(8, 8, BC), 256>>>(x, w_lin, y,
        NB, NB, NB, NB, NB, NB, MM, MM, MM, CH);

    // 2) depthwise conv3 + bias
    conv_bias<<<(int)((BC * MM + 255) / 256), 256>>>(y, w_conv, b_conv, p);

    // 3) RoPE -> Q (== K)
    rope_build<<<(int)(((long)BCN * 64 * NB + 255) / 256), 256>>>(p, q);

    // 4) scores = Q @ Q^T   (scale folded into softmax)
    sgemm_nt<<<dim3(8, 8, BCN), 256>>>(q, q, s,
        NB, NB, HD, HD, HD, NB, QS, QS, MM, BCN);

    // 5) softmax rows, scale = 1/sqrt(1024)
    softmax_rows<<<BCN * NB, 256>>>(s, 1.0f / 32.0f);

    // 6) av = P @ V   (V^T is the p slice: base stride 131072 per bcn, ldb=1024)
    sgemm_nt<<<dim3(1, 8, BCN), 256>>>(s, p, av,
        NB, HD, NB, NB, NB, HD, MM, QS, QS, BCN);

    // 7) merge heads (batched transpose)
    merge_heads<<<dim3(4, 32, BCN), dim3(32, 8)>>>(av, am);

    // 8) out GEMM: out[bc] = am[bc] @ w_out[c]^T
    sgemm_nt<<<dim3(8, 8, BC), 256>>>(am, w_out, out,
        NB, NB, NB, NB, NB, NB, MM, MM, MM, CH);
}

// round 2
// speedup vs baseline: 2.0736x; 2.0736x over previous
#include <cuda_runtime.h>
#include <cuda_bf16.h>
#include <math.h>

// ---------------------------------------------------------------------------
// Problem constants: x(2,4,1024,1024), HEADS=8, D=128, ROT_DIM=64
// ---------------------------------------------------------------------------
#define BATCH   2
#define CH      4
#define BC      (BATCH*CH)        // 8
#define NB      1024              // BINS
#define NH      8                 // heads
#define HD      128               // head dim
#define BCN     (BC*NH)           // 64
#define ROT     64                // rotary dims

// Scratch (static __device__ — no allocations allowed)
__device__ float g_y [BC  * NB * NB];   // proj gemm out (pre-conv)      32MB
__device__ float g_p [BC  * NB * NB];   // conv+bias out ("ph", also V^T) 32MB
__device__ float g_q [BCN * NB * HD];   // roped Q (= K)                  32MB
__device__ float g_s [BCN * NB * NB];   // attention scores              256MB
__device__ float g_av[BCN * NB * HD];   // softmax @ V                    32MB
__device__ float g_am[BC  * NB * NB];   // merged heads (h-major)         32MB

// ---------------------------------------------------------------------------
// tf32 helpers
// ---------------------------------------------------------------------------
__device__ __forceinline__ unsigned f2tf32(float x) {
    unsigned r;
    asm("cvt.rna.tf32.f32 %0, %1;" : "=r"(r) : "f"(x));
    return r;
}

__device__ __forceinline__ void mma_tf32(float* d, const unsigned* a, const unsigned* b) {
    asm volatile(
        "mma.sync.aligned.m16n8k8.row.col.f32.tf32.tf32.f32 "
        "{%0,%1,%2,%3}, {%4,%5,%6,%7}, {%8,%9}, {%0,%1,%2,%3};"
        : "+f"(d[0]), "+f"(d[1]), "+f"(d[2]), "+f"(d[3])
        : "r"(a[0]), "r"(a[1]), "r"(a[2]), "r"(a[3]), "r"(b[0]), "r"(b[1]));
}

// ---------------------------------------------------------------------------
// Batched NT GEMM on tensor cores (tf32, fp32 accumulate):
//   C[m,n] = sum_k A[m*lda+k] * B[n*ldb+k]
// Block tile 128x128, BK=16, 256 threads (8 warps), warp tile 64x32 built
// from 4x4 m16n8k8 mma tiles. Double-buffered smem, register prefetch.
// Smem row stride 20 floats -> frag loads provably bank-conflict-free.
// B batch pointer = B + (batch % modB) * sB  (weights shared across b).
// ---------------------------------------------------------------------------
__global__ __launch_bounds__(256)
void gemm_tf32_nt(const float* __restrict__ A, const float* __restrict__ B,
                  float* __restrict__ C,
                  int M, int N, int K, int lda, int ldb, int ldc,
                  long sA, long sB, long sC, int modB)
{
    const int batch = blockIdx.z;
    A += (long)batch * sA;
    B += (long)(batch % modB) * sB;
    C += (long)batch * sC;

    __shared__ float As[2][128][20];
    __shared__ float Bs[2][128][20];

    const int tid = threadIdx.x;
    const int bm = blockIdx.y * 128;
    const int bn = blockIdx.x * 128;

    // global loader mapping: 128 rows x 16 k, 2 float4 per thread per matrix
    const int lr = tid >> 1;            // row 0..127
    const int lc = (tid & 1) * 8;       // k offset 0 or 8

    const float* Ap = A + (long)(bm + lr) * lda + lc;
    const float* Bp = B + (long)(bn + lr) * ldb + lc;

    const int wid  = tid >> 5;
    const int lane = tid & 31;
    const int wm = wid & 1;             // 0..1  (64 rows each)
    const int wn = wid >> 1;            // 0..3  (32 cols each)
    const int g = lane >> 2;            // 0..7
    const int t = lane & 3;             // 0..3

    float acc[4][4][4];
    #pragma unroll
    for (int i = 0; i < 4; i++)
        #pragma unroll
        for (int j = 0; j < 4; j++)
            #pragma unroll
            for (int r = 0; r < 4; r++) acc[i][j][r] = 0.f;

    float4 pa0, pa1, pb0, pb1;

    // preload tile 0
    pa0 = *(const float4*)(Ap);
    pa1 = *(const float4*)(Ap + 4);
    pb0 = *(const float4*)(Bp);
    pb1 = *(const float4*)(Bp + 4);
    {
        float4 v;
        v.x = __uint_as_float(f2tf32(pa0.x)); v.y = __uint_as_float(f2tf32(pa0.y));
        v.z = __uint_as_float(f2tf32(pa0.z)); v.w = __uint_as_float(f2tf32(pa0.w));
        *(float4*)&As[0][lr][lc] = v;
        v.x = __uint_as_float(f2tf32(pa1.x)); v.y = __uint_as_float(f2tf32(pa1.y));
        v.z = __uint_as_float(f2tf32(pa1.z)); v.w = __uint_as_float(f2tf32(pa1.w));
        *(float4*)&As[0][lr][lc + 4] = v;
        v.x = __uint_as_float(f2tf32(pb0.x)); v.y = __uint_as_float(f2tf32(pb0.y));
        v.z = __uint_as_float(f2tf32(pb0.z)); v.w = __uint_as_float(f2tf32(pb0.w));
        *(float4*)&Bs[0][lr][lc] = v;
        v.x = __uint_as_float(f2tf32(pb1.x)); v.y = __uint_as_float(f2tf32(pb1.y));
        v.z = __uint_as_float(f2tf32(pb1.z)); v.w = __uint_as_float(f2tf32(pb1.w));
        *(float4*)&Bs[0][lr][lc + 4] = v;
    }
    __syncthreads();

    const int iters = K >> 4;
    for (int it = 0; it < iters; ++it) {
        const int c = it & 1;

        // prefetch next tile into registers (overlaps with HMMA below)
        if (it + 1 < iters) {
            const float* ap = Ap + (it + 1) * 16;
            const float* bp = Bp + (it + 1) * 16;
            pa0 = *(const float4*)(ap);
            pa1 = *(const float4*)(ap + 4);
            pb0 = *(const float4*)(bp);
            pb1 = *(const float4*)(bp + 4);
        }

        // compute: 2 k-steps of m16n8k8
        #pragma unroll
        for (int ks = 0; ks < 2; ++ks) {
            const int k0 = ks * 8;
            unsigned af[4][4], bf[4][2];
            #pragma unroll
            for (int mt = 0; mt < 4; mt++) {
                const int m = wm * 64 + mt * 16 + g;
                af[mt][0] = __float_as_uint(As[c][m    ][k0 + t]);
                af[mt][1] = __float_as_uint(As[c][m + 8][k0 + t]);
                af[mt][2] = __float_as_uint(As[c][m    ][k0 + t + 4]);
                af[mt][3] = __float_as_uint(As[c][m + 8][k0 + t + 4]);
            }
            #pragma unroll
            for (int nt = 0; nt < 4; nt++) {
                const int n = wn * 32 + nt * 8 + g;
                bf[nt][0] = __float_as_uint(Bs[c][n][k0 + t]);
                bf[nt][1] = __float_as_uint(Bs[c][n][k0 + t + 4]);
            }
            #pragma unroll
            for (int mt = 0; mt < 4; mt++)
                #pragma unroll
                for (int nt = 0; nt < 4; nt++)
                    mma_tf32(acc[mt][nt], af[mt], bf[nt]);
        }

        // stage next tile into the other smem buffer
        if (it + 1 < iters) {
            const int nc = c ^ 1;
            float4 v;
            v.x = __uint_as_float(f2tf32(pa0.x)); v.y = __uint_as_float(f2tf32(pa0.y));
            v.z = __uint_as_float(f2tf32(pa0.z)); v.w = __uint_as_float(f2tf32(pa0.w));
            *(float4*)&As[nc][lr][lc] = v;
            v.x = __uint_as_float(f2tf32(pa1.x)); v.y = __uint_as_float(f2tf32(pa1.y));
            v.z = __uint_as_float(f2tf32(pa1.z)); v.w = __uint_as_float(f2tf32(pa1.w));
            *(float4*)&As[nc][lr][lc + 4] = v;
            v.x = __uint_as_float(f2tf32(pb0.x)); v.y = __uint_as_float(f2tf32(pb0.y));
            v.z = __uint_as_float(f2tf32(pb0.z)); v.w = __uint_as_float(f2tf32(pb0.w));
            *(float4*)&Bs[nc][lr][lc] = v;
            v.x = __uint_as_float(f2tf32(pb1.x)); v.y = __uint_as_float(f2tf32(pb1.y));
            v.z = __uint_as_float(f2tf32(pb1.z)); v.w = __uint_as_float(f2tf32(pb1.w));
            *(float4*)&Bs[nc][lr][lc + 4] = v;
        }
        __syncthreads();
    }

    // epilogue: c0,c1 at (row, 2t), c2,c3 at (row+8, 2t)
    #pragma unroll
    for (int mt = 0; mt < 4; mt++) {
        const int row = bm + wm * 64 + mt * 16 + g;
        #pragma unroll
        for (int nt = 0; nt < 4; nt++) {
            const int col = bn + wn * 32 + nt * 8 + 2 * t;
            float2 v0 = make_float2(acc[mt][nt][0], acc[mt][nt][1]);
            float2 v1 = make_float2(acc[mt][nt][2], acc[mt][nt][3]);
            *(float2*)(C + (long)row * ldc + col)       = v0;
            *(float2*)(C + (long)(row + 8) * ldc + col) = v1;
        }
    }
}

// ---------------------------------------------------------------------------
// Depthwise conv (kernel 3, pad 1 along last axis) + bias
// ---------------------------------------------------------------------------
__global__ __launch_bounds__(256)
void conv_bias(const float* __restrict__ y, const float* __restrict__ wc,
               const float* __restrict__ bias, float* __restrict__ p)
{
    long idx = (long)blockIdx.x * blockDim.x + threadIdx.x;   // 8M elems
    if (idx >= (long)BC * NB * NB) return;
    int o = (int)(idx & (NB - 1));
    int c = (int)((idx >> 20) & 3);
    float w0 = wc[c*3+0], w1 = wc[c*3+1], w2 = wc[c*3+2];
    float mid = y[idx];
    float lft = (o > 0)      ? y[idx - 1] : 0.f;
    float rgt = (o < NB - 1) ? y[idx + 1] : 0.f;
    p[idx] = fmaf(lft, w0, fmaf(mid, w1, fmaf(rgt, w2, bias[c])));
}

// ---------------------------------------------------------------------------
// RoPE + transpose: Q[bcn][s][d] from p[bc][n*128+d][s].
// ---------------------------------------------------------------------------
__global__ __launch_bounds__(256)
void rope_build(const float* __restrict__ p, float* __restrict__ Q)
{
    long idx = (long)blockIdx.x * blockDim.x + threadIdx.x;   // 4M
    if (idx >= (long)BCN * 64 * NB) return;
    int s   = (int)(idx & (NB - 1));
    int j   = (int)((idx >> 10) & 63);
    int bcn = (int)(idx >> 16);
    int bc = bcn >> 3, n = bcn & 7;

    const float* src = p + ((long)bc * NB + n * HD) * NB + s;
    float*       dst = Q + (long)bcn * (NB * HD) + (long)s * HD;

    if (j < 32) {
        float t0 = src[(2*j + 0) * NB];
        float t1 = src[(2*j + 1) * NB];
        float invf = powf(10000.f, -(float)(2*j) / (float)ROT);
        float ang = (float)s * invf;
        float cs = cosf(ang), sn = sinf(ang);
        dst[2*j + 0] = t0 * cs - t1 * sn;
        dst[2*j + 1] = t1 * cs + t0 * sn;
    } else {
        int d = ROT + (j - 32) * 2;
        dst[d + 0] = src[(d + 0) * NB];
        dst[d + 1] = src[(d + 1) * NB];
    }
}

// ---------------------------------------------------------------------------
// Row softmax with scale (one block per row of 1024)
// ---------------------------------------------------------------------------
__global__ __launch_bounds__(256)
void softmax_rows(float* __restrict__ S, float scale)
{
    float* row = S + (long)blockIdx.x * NB;
    const int t = threadIdx.x;
    __shared__ float red[32];

    float v[4];
    float m = -1e30f;
    #pragma unroll
    for (int i = 0; i < 4; i++) {
        v[i] = row[t + i * 256] * scale;
        m = fmaxf(m, v[i]);
    }
    #pragma unroll
    for (int o = 16; o > 0; o >>= 1) m = fmaxf(m, __shfl_xor_sync(~0u, m, o));
    if ((t & 31) == 0) red[t >> 5] = m;
    __syncthreads();
    if (t < 32) {
        float x = red[t & 7];
        #pragma unroll
        for (int o = 4; o > 0; o >>= 1) x = fmaxf(x, __shfl_xor_sync(~0u, x, o));
        red[t] = x;
    }
    __syncthreads();
    m = red[0];

    float sum = 0.f;
    #pragma unroll
    for (int i = 0; i < 4; i++) { v[i] = __expf(v[i] - m); sum += v[i]; }
    #pragma unroll
    for (int o = 16; o > 0; o >>= 1) sum += __shfl_xor_sync(~0u, sum, o);
    __syncthreads();
    if ((t & 31) == 0) red[t >> 5] = sum;
    __syncthreads();
    if (t < 32) {
        float x = red[t & 7];
        #pragma unroll
        for (int o = 4; o > 0; o >>= 1) x += __shfl_xor_sync(~0u, x, o);
        red[t] = x;
    }
    __syncthreads();
    float inv = 1.f / red[0];
    #pragma unroll
    for (int i = 0; i < 4; i++) row[t + i * 256] = v[i] * inv;
}

// ---------------------------------------------------------------------------
// Merge heads: a_m[bc][n*128+d][s] = av[bcn][s][d]
// ---------------------------------------------------------------------------
__global__ __launch_bounds__(256)
void merge_heads(const float* __restrict__ av, float* __restrict__ am)
{
    __shared__ float tile[32][33];
    int bcn = blockIdx.z;
    const float* src = av + (long)bcn * (NB * HD);
    float*       dst = am + (long)bcn * (NB * HD);
    int d0 = blockIdx.x * 32, s0 = blockIdx.y * 32;
    int tx = threadIdx.x, ty = threadIdx.y;
    #pragma unroll
    for (int i = 0; i < 32; i += 8)
        tile[ty + i][tx] = src[(long)(s0 + ty + i) * HD + d0 + tx];
    __syncthreads();
    #pragma unroll
    for (int i = 0; i < 32; i += 8)
        dst[(long)(d0 + ty + i) * NB + s0 + tx] = tile[tx][ty + i];
}

// ---------------------------------------------------------------------------
// Launch
// ---------------------------------------------------------------------------
extern "C" void kernel_launch(void* const* d_in, const int* in_sizes, int n_in,
                              void* d_out, int out_size)
{
    const float* x      = (const float*)d_in[0];  // (2,4,1024,1024)
    const float* w_lin  = (const float*)d_in[1];  // (4,1024,1024)
    const float* w_conv = (const float*)d_in[2];  // (4,1,1,3)
    const float* b_conv = (const float*)d_in[3];  // (4,)
    const float* w_out  = (const float*)d_in[4];  // (4,1024,1024)
    float* out = (float*)d_out;

    float *y, *p, *q, *s, *av, *am;
    cudaGetSymbolAddress((void**)&y,  g_y);
    cudaGetSymbolAddress((void**)&p,  g_p);
    cudaGetSymbolAddress((void**)&q,  g_q);
    cudaGetSymbolAddress((void**)&s,  g_s);
    cudaGetSymbolAddress((void**)&av, g_av);
    cudaGetSymbolAddress((void**)&am, g_am);

    const long MM = (long)NB * NB;          // 1048576
    const long QS = (long)NB * HD;          // 131072

    // 1) proj GEMM: y[bc] = x[bc] @ w_lin[c]^T
    gemm_tf32_nt<<<dim3(8, 8, BC), 256>>>(x, w_lin, y,
        NB, NB, NB, NB, NB, NB, MM, MM, MM, CH);

    // 2) depthwise conv3 + bias
    conv_bias<<<(int)((BC * MM + 255) / 256), 256>>>(y, w_conv, b_conv, p);

    // 3) RoPE -> Q (== K)
    rope_build<<<(int)(((long)BCN * 64 * NB + 255) / 256), 256>>>(p, q);

    // 4) scores = Q @ Q^T   (scale folded into softmax)
    gemm_tf32_nt<<<dim3(8, 8, BCN), 256>>>(q, q, s,
        NB, NB, HD, HD, HD, NB, QS, QS, MM, BCN);

    // 5) softmax rows, scale = 1/sqrt(1024)
    softmax_rows<<<BCN * NB, 256>>>(s, 1.0f / 32.0f);

    // 6) av = P @ V   (V^T is the p slice: stride 131072 per bcn, ldb=1024)
    gemm_tf32_nt<<<dim3(1, 8, BCN), 256>>>(s, p, av,
        NB, HD, NB, NB, NB, HD, MM, QS, QS, BCN);

    // 7) merge heads (batched transpose)
    merge_heads<<<dim3(4, 32, BCN), dim3(32, 8)>>>(av, am);

    // 8) out GEMM: out[bc] = am[bc] @ w_out[c]^T
    gemm_tf32_nt<<<dim3(8, 8, BC), 256>>>(am, w_out, out,
        NB, NB, NB, NB, NB, NB, MM, MM, MM, CH);
}